// round 2
// baseline (speedup 1.0000x reference)
#include <cuda_runtime.h>
#include <math.h>

// ---------------------------------------------------------------------------
// WeightedPermuteMLP: B=8, SEG=16, DIM=1024, HID=256
// x: (8,16,16,16,1024) fp32.  5 GEMMs M=32768, N=K=1024 + tiny gating MLP.
//
// Unified addressing: m = (b,a1,a2,a3) nibbles, k = t*64 + s:
//   addr(m,k) = base(m) + (k>>6)*stride_t + (k&63)
//   base(m)   = b*4194304 + a1*s1 + a2*s2 + a3*s3
// Output of each branch uses the SAME mapping with n in place of k.
// ---------------------------------------------------------------------------

#define NPOSC 33554432   // 8*16*16*16*1024

__device__ __align__(256) float g_h[NPOSC];
__device__ __align__(256) float g_w[NPOSC];
__device__ __align__(256) float g_d[NPOSC];
__device__ __align__(256) float g_c[NPOSC];
__device__ __align__(256) float g_partial[8 * 32 * 1024];
__device__ __align__(256) float g_sum[8 * 1024];
__device__ __align__(256) float g_a[4 * 8 * 1024];   // [q][b][chan]

// ---------------------------------------------------------------------------
// Branch GEMM: Y(m,n) = sum_k A(m,k) * W[k*1024+n] + bias[n]
// A gathered from x via (s1,s2,s3,st); Y scattered with same mapping.
// ---------------------------------------------------------------------------
__device__ __forceinline__ int row_base(int m, int s1, int s2, int s3) {
    return (m >> 12) * 4194304 + ((m >> 8) & 15) * s1 + ((m >> 4) & 15) * s2 + (m & 15) * s3;
}

__global__ __launch_bounds__(256, 2)
void gemm_perm(const float* __restrict__ X, const float* __restrict__ Wm,
               const float* __restrict__ bias, int sel,
               int s1, int s2, int s3, int st)
{
    float* __restrict__ Y = (sel == 0) ? g_h : (sel == 1) ? g_w : (sel == 2) ? g_d : g_c;

    __shared__ float As[16][132];
    __shared__ float Bs[16][128];

    const int tid = threadIdx.x;
    const int bm = blockIdx.y * 128;
    const int bn = blockIdx.x * 128;

    // A loader: thread -> (row, k-subgroup)
    const int ar  = tid >> 2;         // 0..63
    const int akg = (tid & 3) * 4;    // 0,4,8,12
    const int base0 = row_base(bm + ar,      s1, s2, s3);
    const int base1 = row_base(bm + ar + 64, s1, s2, s3);

    // B loader
    const int brow = tid >> 5;        // 0..7
    const int bcol = (tid & 31) * 4;

    // compute mapping
    const int tn = (tid & 15) * 8;
    const int tm = (tid >> 4) * 8;

    float acc[8][8];
#pragma unroll
    for (int i = 0; i < 8; i++)
#pragma unroll
        for (int j = 0; j < 8; j++) acc[i][j] = 0.0f;

    for (int k0 = 0; k0 < 1024; k0 += 16) {
        // ---- load A tile (128 x 16) ----
        {
            const int k = k0 + akg;
            const int off = (k >> 6) * st + (k & 63);
            float4 va = *reinterpret_cast<const float4*>(X + base0 + off);
            float4 vb = *reinterpret_cast<const float4*>(X + base1 + off);
            As[akg + 0][ar] = va.x; As[akg + 1][ar] = va.y;
            As[akg + 2][ar] = va.z; As[akg + 3][ar] = va.w;
            As[akg + 0][ar + 64] = vb.x; As[akg + 1][ar + 64] = vb.y;
            As[akg + 2][ar + 64] = vb.z; As[akg + 3][ar + 64] = vb.w;
        }
        // ---- load B tile (16 x 128) ----
        {
            float4 v0 = *reinterpret_cast<const float4*>(Wm + (k0 + brow) * 1024 + bn + bcol);
            float4 v1 = *reinterpret_cast<const float4*>(Wm + (k0 + brow + 8) * 1024 + bn + bcol);
            *reinterpret_cast<float4*>(&Bs[brow][bcol])     = v0;
            *reinterpret_cast<float4*>(&Bs[brow + 8][bcol]) = v1;
        }
        __syncthreads();

#pragma unroll
        for (int kk = 0; kk < 16; kk++) {
            float a[8], b[8];
            *reinterpret_cast<float4*>(&a[0]) = *reinterpret_cast<const float4*>(&As[kk][tm]);
            *reinterpret_cast<float4*>(&a[4]) = *reinterpret_cast<const float4*>(&As[kk][tm + 4]);
            *reinterpret_cast<float4*>(&b[0]) = *reinterpret_cast<const float4*>(&Bs[kk][tn]);
            *reinterpret_cast<float4*>(&b[4]) = *reinterpret_cast<const float4*>(&Bs[kk][tn + 4]);
#pragma unroll
            for (int i = 0; i < 8; i++)
#pragma unroll
                for (int j = 0; j < 8; j++)
                    acc[i][j] += a[i] * b[j];
        }
        __syncthreads();
    }

    // ---- epilogue: scatter with bias ----
#pragma unroll
    for (int i = 0; i < 8; i++) {
        const int m = bm + tm + i;
        const int rb = row_base(m, s1, s2, s3);
#pragma unroll
        for (int j = 0; j < 8; j += 4) {
            const int n = bn + tn + j;
            const int off = (n >> 6) * st + (n & 63);
            float4 bv = *reinterpret_cast<const float4*>(bias + n);
            float4 o;
            o.x = acc[i][j + 0] + bv.x;
            o.y = acc[i][j + 1] + bv.y;
            o.z = acc[i][j + 2] + bv.z;
            o.w = acc[i][j + 3] + bv.w;
            *reinterpret_cast<float4*>(Y + rb + off) = o;
        }
    }
}

// ---------------------------------------------------------------------------
// Deterministic 2-stage mean over positions of (h+w+d+c)
// ---------------------------------------------------------------------------
__global__ void reduce1()
{
    const int b = blockIdx.x, pc = blockIdx.y, ch = threadIdx.x; // 1024 threads
    const int base = b * 4194304 + pc * 131072 + ch;
    float s = 0.0f;
#pragma unroll 4
    for (int p = 0; p < 128; p++) {
        const int idx = base + p * 1024;
        s += g_h[idx] + g_w[idx] + g_d[idx] + g_c[idx];
    }
    g_partial[(b * 32 + pc) * 1024 + ch] = s;
}

__global__ void reduce2()
{
    const int b = blockIdx.x, ch = threadIdx.x;
    float s = 0.0f;
#pragma unroll
    for (int pc = 0; pc < 32; pc++) s += g_partial[(b * 32 + pc) * 1024 + ch];
    g_sum[b * 1024 + ch] = s;
}

// ---------------------------------------------------------------------------
// Gating MLP + softmax: a = softmax_4( gelu(mean @ w1 + b1) @ w2 + b2 )
// one block per batch, 256 threads
// ---------------------------------------------------------------------------
__global__ __launch_bounds__(256)
void mlp_kernel(const float* __restrict__ w1, const float* __restrict__ b1,
                const float* __restrict__ w2, const float* __restrict__ b2)
{
    __shared__ float sv[1024];
    __shared__ float tt[256];
    __shared__ float zs[4096];

    const int b = blockIdx.x, tid = threadIdx.x;

    for (int c = tid; c < 1024; c += 256)
        sv[c] = g_sum[b * 1024 + c] * (1.0f / 4096.0f);
    __syncthreads();

    {
        float acc = b1[tid];
        for (int k = 0; k < 1024; k++) acc += sv[k] * w1[k * 256 + tid];
        // exact GELU
        tt[tid] = 0.5f * acc * (1.0f + erff(acc * 0.7071067811865476f));
    }
    __syncthreads();

    for (int n = tid; n < 4096; n += 256) {
        float acc = b2[n];
#pragma unroll 8
        for (int k = 0; k < 256; k++) acc += tt[k] * w2[k * 4096 + n];
        zs[n] = acc;
    }
    __syncthreads();

    for (int c = tid; c < 1024; c += 256) {
        const float v0 = zs[4 * c + 0], v1 = zs[4 * c + 1];
        const float v2 = zs[4 * c + 2], v3 = zs[4 * c + 3];
        const float mx = fmaxf(fmaxf(v0, v1), fmaxf(v2, v3));
        const float e0 = expf(v0 - mx), e1 = expf(v1 - mx);
        const float e2 = expf(v2 - mx), e3 = expf(v3 - mx);
        const float inv = 1.0f / (e0 + e1 + e2 + e3);
        g_a[0 * 8192 + b * 1024 + c] = e0 * inv;
        g_a[1 * 8192 + b * 1024 + c] = e1 * inv;
        g_a[2 * 8192 + b * 1024 + c] = e2 * inv;
        g_a[3 * 8192 + b * 1024 + c] = e3 * inv;
    }
}

// ---------------------------------------------------------------------------
// Final GEMM with fused weighted combine:
// out = (h*a0 + w*a1 + d*a2 + c*a3) @ wp + bp    (contiguous layout)
// ---------------------------------------------------------------------------
__global__ __launch_bounds__(256, 2)
void gemm_final(const float* __restrict__ Wm, const float* __restrict__ bias,
                float* __restrict__ Y)
{
    __shared__ float As[16][132];
    __shared__ float Bs[16][128];

    const int tid = threadIdx.x;
    const int bm = blockIdx.y * 128;
    const int bn = blockIdx.x * 128;
    const int bb = bm >> 12;                     // batch is constant per block

    const int ar  = tid >> 2;
    const int akg = (tid & 3) * 4;
    const int m0 = bm + ar, m1 = bm + ar + 64;

    const int brow = tid >> 5;
    const int bcol = (tid & 31) * 4;

    const int tn = (tid & 15) * 8;
    const int tm = (tid >> 4) * 8;

    float acc[8][8];
#pragma unroll
    for (int i = 0; i < 8; i++)
#pragma unroll
        for (int j = 0; j < 8; j++) acc[i][j] = 0.0f;

    for (int k0 = 0; k0 < 1024; k0 += 16) {
        {
            const int k = k0 + akg;
            const int aw = bb * 1024 + k;
            float4 w0 = *reinterpret_cast<const float4*>(g_a + 0 * 8192 + aw);
            float4 w1 = *reinterpret_cast<const float4*>(g_a + 1 * 8192 + aw);
            float4 w2 = *reinterpret_cast<const float4*>(g_a + 2 * 8192 + aw);
            float4 w3 = *reinterpret_cast<const float4*>(g_a + 3 * 8192 + aw);

            const int i0 = m0 * 1024 + k;
            const int i1 = m1 * 1024 + k;
            float4 h0 = *reinterpret_cast<const float4*>(g_h + i0);
            float4 ww0 = *reinterpret_cast<const float4*>(g_w + i0);
            float4 d0 = *reinterpret_cast<const float4*>(g_d + i0);
            float4 c0 = *reinterpret_cast<const float4*>(g_c + i0);
            float4 h1 = *reinterpret_cast<const float4*>(g_h + i1);
            float4 ww1 = *reinterpret_cast<const float4*>(g_w + i1);
            float4 d1 = *reinterpret_cast<const float4*>(g_d + i1);
            float4 c1 = *reinterpret_cast<const float4*>(g_c + i1);

            As[akg + 0][ar] = h0.x * w0.x + ww0.x * w1.x + d0.x * w2.x + c0.x * w3.x;
            As[akg + 1][ar] = h0.y * w0.y + ww0.y * w1.y + d0.y * w2.y + c0.y * w3.y;
            As[akg + 2][ar] = h0.z * w0.z + ww0.z * w1.z + d0.z * w2.z + c0.z * w3.z;
            As[akg + 3][ar] = h0.w * w0.w + ww0.w * w1.w + d0.w * w2.w + c0.w * w3.w;
            As[akg + 0][ar + 64] = h1.x * w0.x + ww1.x * w1.x + d1.x * w2.x + c1.x * w3.x;
            As[akg + 1][ar + 64] = h1.y * w0.y + ww1.y * w1.y + d1.y * w2.y + c1.y * w3.y;
            As[akg + 2][ar + 64] = h1.z * w0.z + ww1.z * w1.z + d1.z * w2.z + c1.z * w3.z;
            As[akg + 3][ar + 64] = h1.w * w0.w + ww1.w * w1.w + d1.w * w2.w + c1.w * w3.w;
        }
        {
            float4 v0 = *reinterpret_cast<const float4*>(Wm + (k0 + brow) * 1024 + bn + bcol);
            float4 v1 = *reinterpret_cast<const float4*>(Wm + (k0 + brow + 8) * 1024 + bn + bcol);
            *reinterpret_cast<float4*>(&Bs[brow][bcol])     = v0;
            *reinterpret_cast<float4*>(&Bs[brow + 8][bcol]) = v1;
        }
        __syncthreads();

#pragma unroll
        for (int kk = 0; kk < 16; kk++) {
            float a[8], b[8];
            *reinterpret_cast<float4*>(&a[0]) = *reinterpret_cast<const float4*>(&As[kk][tm]);
            *reinterpret_cast<float4*>(&a[4]) = *reinterpret_cast<const float4*>(&As[kk][tm + 4]);
            *reinterpret_cast<float4*>(&b[0]) = *reinterpret_cast<const float4*>(&Bs[kk][tn]);
            *reinterpret_cast<float4*>(&b[4]) = *reinterpret_cast<const float4*>(&Bs[kk][tn + 4]);
#pragma unroll
            for (int i = 0; i < 8; i++)
#pragma unroll
                for (int j = 0; j < 8; j++)
                    acc[i][j] += a[i] * b[j];
        }
        __syncthreads();
    }

#pragma unroll
    for (int i = 0; i < 8; i++) {
        const int m = bm + tm + i;
#pragma unroll
        for (int j = 0; j < 8; j += 4) {
            const int n = bn + tn + j;
            float4 bv = *reinterpret_cast<const float4*>(bias + n);
            float4 o;
            o.x = acc[i][j + 0] + bv.x;
            o.y = acc[i][j + 1] + bv.y;
            o.z = acc[i][j + 2] + bv.z;
            o.w = acc[i][j + 3] + bv.w;
            *reinterpret_cast<float4*>(Y + m * 1024 + n) = o;
        }
    }
}

// ---------------------------------------------------------------------------
extern "C" void kernel_launch(void* const* d_in, const int* in_sizes, int n_in,
                              void* d_out, int out_size)
{
    const float* x  = (const float*)d_in[0];
    const float* wh = (const float*)d_in[1];
    const float* bh = (const float*)d_in[2];
    const float* ww = (const float*)d_in[3];
    const float* bw = (const float*)d_in[4];
    const float* wd = (const float*)d_in[5];
    const float* bd = (const float*)d_in[6];
    const float* wc = (const float*)d_in[7];
    const float* bc = (const float*)d_in[8];
    const float* w1 = (const float*)d_in[9];
    const float* b1 = (const float*)d_in[10];
    const float* w2 = (const float*)d_in[11];
    const float* b2 = (const float*)d_in[12];
    const float* wp = (const float*)d_in[13];
    const float* bp = (const float*)d_in[14];
    float* out = (float*)d_out;

    dim3 grid(8, 256);

    // branch GEMMs (h, w, d, c) — unified kernel, different address mappings
    gemm_perm<<<grid, 256>>>(x, wh, bh, 0, 64,     16384, 1024,  262144);
    gemm_perm<<<grid, 256>>>(x, ww, bw, 1, 262144, 64,    1024,  16384);
    gemm_perm<<<grid, 256>>>(x, wd, bd, 2, 262144, 16384, 64,    1024);
    gemm_perm<<<grid, 256>>>(x, wc, bc, 3, 262144, 16384, 1024,  64);

    // mean over positions (deterministic 2-stage)
    reduce1<<<dim3(8, 32), 1024>>>();
    reduce2<<<8, 1024>>>();

    // gating MLP + softmax
    mlp_kernel<<<8, 256>>>(w1, b1, w2, b2);

    // fused weighted-combine + final projection
    gemm_final<<<grid, 256>>>(wp, bp, out);
}

// round 3
// speedup vs baseline: 1.0009x; 1.0009x over previous
#include <cuda_runtime.h>
#include <math.h>

// ---------------------------------------------------------------------------
// WeightedPermuteMLP: B=8, SEG=16, DIM=1024, HID=256
// x: (8,16,16,16,1024) fp32.  5 GEMMs M=32768, N=K=1024 + tiny gating MLP.
//
// Unified addressing: m = (b,a1,a2,a3) nibbles, k = t*64 + s:
//   addr(m,k) = base(m) + (k>>6)*stride_t + (k&63)
//   base(m)   = b*4194304 + a1*s1 + a2*s2 + a3*s3
// Output of each branch uses the SAME mapping with n in place of k.
// ---------------------------------------------------------------------------

#define NPOSC 33554432   // 8*16*16*16*1024

__device__ __align__(256) float g_h[NPOSC];
__device__ __align__(256) float g_w[NPOSC];
__device__ __align__(256) float g_d[NPOSC];
__device__ __align__(256) float g_c[NPOSC];
__device__ __align__(256) float g_partial[8 * 32 * 1024];
__device__ __align__(256) float g_sum[8 * 1024];
__device__ __align__(256) float g_a[4 * 8 * 1024];   // [q][b][chan]

// ---------------------------------------------------------------------------
// Branch GEMM: Y(m,n) = sum_k A(m,k) * W[k*1024+n] + bias[n]
// A gathered from x via (s1,s2,s3,st); Y scattered with same mapping.
// ---------------------------------------------------------------------------
__device__ __forceinline__ int row_base(int m, int s1, int s2, int s3) {
    return (m >> 12) * 4194304 + ((m >> 8) & 15) * s1 + ((m >> 4) & 15) * s2 + (m & 15) * s3;
}

__global__ __launch_bounds__(256, 2)
void gemm_perm(const float* __restrict__ X, const float* __restrict__ Wm,
               const float* __restrict__ bias, int sel,
               int s1, int s2, int s3, int st)
{
    float* __restrict__ Y = (sel == 0) ? g_h : (sel == 1) ? g_w : (sel == 2) ? g_d : g_c;

    __shared__ float As[16][132];
    __shared__ float Bs[16][128];

    const int tid = threadIdx.x;
    const int bm = blockIdx.y * 128;
    const int bn = blockIdx.x * 128;

    // A loader: thread -> (row, k-subgroup)
    const int ar  = tid >> 2;         // 0..63
    const int akg = (tid & 3) * 4;    // 0,4,8,12
    const int base0 = row_base(bm + ar,      s1, s2, s3);
    const int base1 = row_base(bm + ar + 64, s1, s2, s3);

    // B loader
    const int brow = tid >> 5;        // 0..7
    const int bcol = (tid & 31) * 4;

    // compute mapping
    const int tn = (tid & 15) * 8;
    const int tm = (tid >> 4) * 8;

    float acc[8][8];
#pragma unroll
    for (int i = 0; i < 8; i++)
#pragma unroll
        for (int j = 0; j < 8; j++) acc[i][j] = 0.0f;

    for (int k0 = 0; k0 < 1024; k0 += 16) {
        // ---- load A tile (128 x 16) ----
        {
            const int k = k0 + akg;
            const int off = (k >> 6) * st + (k & 63);
            float4 va = *reinterpret_cast<const float4*>(X + base0 + off);
            float4 vb = *reinterpret_cast<const float4*>(X + base1 + off);
            As[akg + 0][ar] = va.x; As[akg + 1][ar] = va.y;
            As[akg + 2][ar] = va.z; As[akg + 3][ar] = va.w;
            As[akg + 0][ar + 64] = vb.x; As[akg + 1][ar + 64] = vb.y;
            As[akg + 2][ar + 64] = vb.z; As[akg + 3][ar + 64] = vb.w;
        }
        // ---- load B tile (16 x 128) ----
        {
            float4 v0 = *reinterpret_cast<const float4*>(Wm + (k0 + brow) * 1024 + bn + bcol);
            float4 v1 = *reinterpret_cast<const float4*>(Wm + (k0 + brow + 8) * 1024 + bn + bcol);
            *reinterpret_cast<float4*>(&Bs[brow][bcol])     = v0;
            *reinterpret_cast<float4*>(&Bs[brow + 8][bcol]) = v1;
        }
        __syncthreads();

#pragma unroll
        for (int kk = 0; kk < 16; kk++) {
            float a[8], b[8];
            *reinterpret_cast<float4*>(&a[0]) = *reinterpret_cast<const float4*>(&As[kk][tm]);
            *reinterpret_cast<float4*>(&a[4]) = *reinterpret_cast<const float4*>(&As[kk][tm + 4]);
            *reinterpret_cast<float4*>(&b[0]) = *reinterpret_cast<const float4*>(&Bs[kk][tn]);
            *reinterpret_cast<float4*>(&b[4]) = *reinterpret_cast<const float4*>(&Bs[kk][tn + 4]);
#pragma unroll
            for (int i = 0; i < 8; i++)
#pragma unroll
                for (int j = 0; j < 8; j++)
                    acc[i][j] += a[i] * b[j];
        }
        __syncthreads();
    }

    // ---- epilogue: scatter with bias ----
#pragma unroll
    for (int i = 0; i < 8; i++) {
        const int m = bm + tm + i;
        const int rb = row_base(m, s1, s2, s3);
#pragma unroll
        for (int j = 0; j < 8; j += 4) {
            const int n = bn + tn + j;
            const int off = (n >> 6) * st + (n & 63);
            float4 bv = *reinterpret_cast<const float4*>(bias + n);
            float4 o;
            o.x = acc[i][j + 0] + bv.x;
            o.y = acc[i][j + 1] + bv.y;
            o.z = acc[i][j + 2] + bv.z;
            o.w = acc[i][j + 3] + bv.w;
            *reinterpret_cast<float4*>(Y + rb + off) = o;
        }
    }
}

// ---------------------------------------------------------------------------
// Deterministic 2-stage mean over positions of (h+w+d+c)
// ---------------------------------------------------------------------------
__global__ void reduce1()
{
    const int b = blockIdx.x, pc = blockIdx.y, ch = threadIdx.x; // 1024 threads
    const int base = b * 4194304 + pc * 131072 + ch;
    float s = 0.0f;
#pragma unroll 4
    for (int p = 0; p < 128; p++) {
        const int idx = base + p * 1024;
        s += g_h[idx] + g_w[idx] + g_d[idx] + g_c[idx];
    }
    g_partial[(b * 32 + pc) * 1024 + ch] = s;
}

__global__ void reduce2()
{
    const int b = blockIdx.x, ch = threadIdx.x;
    float s = 0.0f;
#pragma unroll
    for (int pc = 0; pc < 32; pc++) s += g_partial[(b * 32 + pc) * 1024 + ch];
    g_sum[b * 1024 + ch] = s;
}

// ---------------------------------------------------------------------------
// Gating MLP + softmax: a = softmax_4( gelu(mean @ w1 + b1) @ w2 + b2 )
// one block per batch, 256 threads
// ---------------------------------------------------------------------------
__global__ __launch_bounds__(256)
void mlp_kernel(const float* __restrict__ w1, const float* __restrict__ b1,
                const float* __restrict__ w2, const float* __restrict__ b2)
{
    __shared__ float sv[1024];
    __shared__ float tt[256];
    __shared__ float zs[4096];

    const int b = blockIdx.x, tid = threadIdx.x;

    for (int c = tid; c < 1024; c += 256)
        sv[c] = g_sum[b * 1024 + c] * (1.0f / 4096.0f);
    __syncthreads();

    {
        float acc = b1[tid];
        for (int k = 0; k < 1024; k++) acc += sv[k] * w1[k * 256 + tid];
        // exact GELU
        tt[tid] = 0.5f * acc * (1.0f + erff(acc * 0.7071067811865476f));
    }
    __syncthreads();

    for (int n = tid; n < 4096; n += 256) {
        float acc = b2[n];
#pragma unroll 8
        for (int k = 0; k < 256; k++) acc += tt[k] * w2[k * 4096 + n];
        zs[n] = acc;
    }
    __syncthreads();

    for (int c = tid; c < 1024; c += 256) {
        const float v0 = zs[4 * c + 0], v1 = zs[4 * c + 1];
        const float v2 = zs[4 * c + 2], v3 = zs[4 * c + 3];
        const float mx = fmaxf(fmaxf(v0, v1), fmaxf(v2, v3));
        const float e0 = expf(v0 - mx), e1 = expf(v1 - mx);
        const float e2 = expf(v2 - mx), e3 = expf(v3 - mx);
        const float inv = 1.0f / (e0 + e1 + e2 + e3);
        g_a[0 * 8192 + b * 1024 + c] = e0 * inv;
        g_a[1 * 8192 + b * 1024 + c] = e1 * inv;
        g_a[2 * 8192 + b * 1024 + c] = e2 * inv;
        g_a[3 * 8192 + b * 1024 + c] = e3 * inv;
    }
}

// ---------------------------------------------------------------------------
// Final GEMM with fused weighted combine:
// out = (h*a0 + w*a1 + d*a2 + c*a3) @ wp + bp    (contiguous layout)
// ---------------------------------------------------------------------------
__global__ __launch_bounds__(256, 2)
void gemm_final(const float* __restrict__ Wm, const float* __restrict__ bias,
                float* __restrict__ Y)
{
    __shared__ float As[16][132];
    __shared__ float Bs[16][128];

    const int tid = threadIdx.x;
    const int bm = blockIdx.y * 128;
    const int bn = blockIdx.x * 128;
    const int bb = bm >> 12;                     // batch is constant per block

    const int ar  = tid >> 2;
    const int akg = (tid & 3) * 4;
    const int m0 = bm + ar, m1 = bm + ar + 64;

    const int brow = tid >> 5;
    const int bcol = (tid & 31) * 4;

    const int tn = (tid & 15) * 8;
    const int tm = (tid >> 4) * 8;

    float acc[8][8];
#pragma unroll
    for (int i = 0; i < 8; i++)
#pragma unroll
        for (int j = 0; j < 8; j++) acc[i][j] = 0.0f;

    for (int k0 = 0; k0 < 1024; k0 += 16) {
        {
            const int k = k0 + akg;
            const int aw = bb * 1024 + k;
            float4 w0 = *reinterpret_cast<const float4*>(g_a + 0 * 8192 + aw);
            float4 w1 = *reinterpret_cast<const float4*>(g_a + 1 * 8192 + aw);
            float4 w2 = *reinterpret_cast<const float4*>(g_a + 2 * 8192 + aw);
            float4 w3 = *reinterpret_cast<const float4*>(g_a + 3 * 8192 + aw);

            const int i0 = m0 * 1024 + k;
            const int i1 = m1 * 1024 + k;
            float4 h0 = *reinterpret_cast<const float4*>(g_h + i0);
            float4 ww0 = *reinterpret_cast<const float4*>(g_w + i0);
            float4 d0 = *reinterpret_cast<const float4*>(g_d + i0);
            float4 c0 = *reinterpret_cast<const float4*>(g_c + i0);
            float4 h1 = *reinterpret_cast<const float4*>(g_h + i1);
            float4 ww1 = *reinterpret_cast<const float4*>(g_w + i1);
            float4 d1 = *reinterpret_cast<const float4*>(g_d + i1);
            float4 c1 = *reinterpret_cast<const float4*>(g_c + i1);

            As[akg + 0][ar] = h0.x * w0.x + ww0.x * w1.x + d0.x * w2.x + c0.x * w3.x;
            As[akg + 1][ar] = h0.y * w0.y + ww0.y * w1.y + d0.y * w2.y + c0.y * w3.y;
            As[akg + 2][ar] = h0.z * w0.z + ww0.z * w1.z + d0.z * w2.z + c0.z * w3.z;
            As[akg + 3][ar] = h0.w * w0.w + ww0.w * w1.w + d0.w * w2.w + c0.w * w3.w;
            As[akg + 0][ar + 64] = h1.x * w0.x + ww1.x * w1.x + d1.x * w2.x + c1.x * w3.x;
            As[akg + 1][ar + 64] = h1.y * w0.y + ww1.y * w1.y + d1.y * w2.y + c1.y * w3.y;
            As[akg + 2][ar + 64] = h1.z * w0.z + ww1.z * w1.z + d1.z * w2.z + c1.z * w3.z;
            As[akg + 3][ar + 64] = h1.w * w0.w + ww1.w * w1.w + d1.w * w2.w + c1.w * w3.w;
        }
        {
            float4 v0 = *reinterpret_cast<const float4*>(Wm + (k0 + brow) * 1024 + bn + bcol);
            float4 v1 = *reinterpret_cast<const float4*>(Wm + (k0 + brow + 8) * 1024 + bn + bcol);
            *reinterpret_cast<float4*>(&Bs[brow][bcol])     = v0;
            *reinterpret_cast<float4*>(&Bs[brow + 8][bcol]) = v1;
        }
        __syncthreads();

#pragma unroll
        for (int kk = 0; kk < 16; kk++) {
            float a[8], b[8];
            *reinterpret_cast<float4*>(&a[0]) = *reinterpret_cast<const float4*>(&As[kk][tm]);
            *reinterpret_cast<float4*>(&a[4]) = *reinterpret_cast<const float4*>(&As[kk][tm + 4]);
            *reinterpret_cast<float4*>(&b[0]) = *reinterpret_cast<const float4*>(&Bs[kk][tn]);
            *reinterpret_cast<float4*>(&b[4]) = *reinterpret_cast<const float4*>(&Bs[kk][tn + 4]);
#pragma unroll
            for (int i = 0; i < 8; i++)
#pragma unroll
                for (int j = 0; j < 8; j++)
                    acc[i][j] += a[i] * b[j];
        }
        __syncthreads();
    }

#pragma unroll
    for (int i = 0; i < 8; i++) {
        const int m = bm + tm + i;
#pragma unroll
        for (int j = 0; j < 8; j += 4) {
            const int n = bn + tn + j;
            float4 bv = *reinterpret_cast<const float4*>(bias + n);
            float4 o;
            o.x = acc[i][j + 0] + bv.x;
            o.y = acc[i][j + 1] + bv.y;
            o.z = acc[i][j + 2] + bv.z;
            o.w = acc[i][j + 3] + bv.w;
            *reinterpret_cast<float4*>(Y + m * 1024 + n) = o;
        }
    }
}

// ---------------------------------------------------------------------------
extern "C" void kernel_launch(void* const* d_in, const int* in_sizes, int n_in,
                              void* d_out, int out_size)
{
    const float* x  = (const float*)d_in[0];
    const float* wh = (const float*)d_in[1];
    const float* bh = (const float*)d_in[2];
    const float* ww = (const float*)d_in[3];
    const float* bw = (const float*)d_in[4];
    const float* wd = (const float*)d_in[5];
    const float* bd = (const float*)d_in[6];
    const float* wc = (const float*)d_in[7];
    const float* bc = (const float*)d_in[8];
    const float* w1 = (const float*)d_in[9];
    const float* b1 = (const float*)d_in[10];
    const float* w2 = (const float*)d_in[11];
    const float* b2 = (const float*)d_in[12];
    const float* wp = (const float*)d_in[13];
    const float* bp = (const float*)d_in[14];
    float* out = (float*)d_out;

    dim3 grid(8, 256);

    // branch GEMMs (h, w, d, c) — unified kernel, different address mappings
    gemm_perm<<<grid, 256>>>(x, wh, bh, 0, 64,     16384, 1024,  262144);
    gemm_perm<<<grid, 256>>>(x, ww, bw, 1, 262144, 64,    1024,  16384);
    gemm_perm<<<grid, 256>>>(x, wd, bd, 2, 262144, 16384, 64,    1024);
    gemm_perm<<<grid, 256>>>(x, wc, bc, 3, 262144, 16384, 1024,  64);

    // mean over positions (deterministic 2-stage)
    reduce1<<<dim3(8, 32), 1024>>>();
    reduce2<<<8, 1024>>>();

    // gating MLP + softmax
    mlp_kernel<<<8, 256>>>(w1, b1, w2, b2);

    // fused weighted-combine + final projection
    gemm_final<<<grid, 256>>>(wp, bp, out);
}

// round 8
// speedup vs baseline: 1.3362x; 1.3350x over previous
#include <cuda_runtime.h>
#include <cuda_bf16.h>
#include <mma.h>
#include <cstdint>
#include <math.h>

using namespace nvcuda;

// ===========================================================================
// WeightedPermuteMLP — split-bf16 wmma with IN-KERNEL conversion.
// B=8, SEG=16, DIM=1024, HID=256.  5 GEMMs M=32768, N=K=1024.
// No pre-pass converts, no bf16 global tables: fp32 loads (R1-proven
// addressing) -> register split to bf16 hi/lo -> smem -> wmma (3 products).
// Unified addressing, m nibbles (b,i1,i2,i3), k = t*64 + s:
//   addr(m,k) = base(m) + (k>>6)*st + (k&63);  base = b*4M + i1*s1+i2*s2+i3*s3
// ===========================================================================

#define NELEM 33554432

__device__ __align__(256) float g_h[NELEM];
__device__ __align__(256) float g_w[NELEM];
__device__ __align__(256) float g_d[NELEM];
__device__ __align__(256) float g_c[NELEM];
__device__ __align__(256) float g_partial[8 * 32 * 1024];
__device__ __align__(256) float g_sum[8 * 1024];
__device__ __align__(256) float g_a[4 * 8 * 1024];   // [q][b][chan]

__device__ __forceinline__ int row_base(int m, int s1, int s2, int s3) {
    return (m >> 12) * 4194304 + ((m >> 8) & 15) * s1 + ((m >> 4) & 15) * s2 + (m & 15) * s3;
}

// split 16 fp32 -> bf16 hi/lo, write as bf16x2 pairs
__device__ __forceinline__ void cvt16(const float* f, __nv_bfloat16* sh, __nv_bfloat16* sl)
{
#pragma unroll
    for (int j = 0; j < 8; j++) {
        const float x0 = f[2*j], x1 = f[2*j+1];
        const __nv_bfloat16 h0 = __float2bfloat16_rn(x0);
        const __nv_bfloat16 h1 = __float2bfloat16_rn(x1);
        ((__nv_bfloat162*)sh)[j] = __halves2bfloat162(h0, h1);
        ((__nv_bfloat162*)sl)[j] = __halves2bfloat162(
            __float2bfloat16_rn(x0 - __bfloat162float(h0)),
            __float2bfloat16_rn(x1 - __bfloat162float(h1)));
    }
}

// ---------------------------------------------------------------------------
// Unified wmma GEMM: block 128x128, BK=32, 8 warps (2m x 4n), warp tile 64x32.
//   sel 0..3: Y = branch buffer, A = gather from X via (s1,s2,s3,st)
//   sel 4   : Y = outF (contiguous), A = h*a0+w*a1+d*a2+c*a3 (fused combine)
// B read directly from fp32 W[k][n]; wmma matrix_b row_major.
// Static smem: A 2*5120 + B 2*4352 bf16 = 37888 B.
// ---------------------------------------------------------------------------
#define KPAD 40       // A smem row stride (32 data + 8 pad), bf16
#define NPAD 136      // B smem row stride (128 data + 8 pad), bf16
#define A_ELE (128 * KPAD)
#define B_ELE (32 * NPAD)
#define EPAD 36       // f32 epilogue row stride

__global__ __launch_bounds__(256)
void gemm_wmma(const float* __restrict__ X, const float* __restrict__ Wm,
               const float* __restrict__ bias, int sel,
               int s1, int s2, int s3, int st, float* __restrict__ outF)
{
    __shared__ __align__(256) __nv_bfloat16 smem[2 * A_ELE + 2 * B_ELE];
    __nv_bfloat16* sAH = smem;
    __nv_bfloat16* sAL = sAH + A_ELE;
    __nv_bfloat16* sBH = sAL + A_ELE;
    __nv_bfloat16* sBL = sBH + B_ELE;

    const int tid = threadIdx.x;
    const int wid = tid >> 5;
    const int lane = tid & 31;
    const int bm = blockIdx.y * 128;
    const int bn = blockIdx.x * 128;
    float* Y = (sel == 0) ? g_h : (sel == 1) ? g_w : (sel == 2) ? g_d
             : (sel == 3) ? g_c : outF;

    // ---- A loader: thread -> (row r = tid>>1, k-half lk = (tid&1)*16) ----
    const int r  = tid >> 1;
    const int lk = (tid & 1) * 16;
    const int abase = row_base(bm + r, s1, s2, s3) + lk;   // branch gather base
    const int cbase = (bm + r) * 1024 + lk;                // contiguous (final)
    const int awbase = ((bm >> 12) << 10) + lk;            // g_a row for batch
    const int sA = r * KPAD + lk;

    // ---- B loader: thread -> (krow = tid>>3, ncol = (tid&7)*16) ----
    const int krow = tid >> 3;
    const int ncol = (tid & 7) * 16;
    const int bbase = krow * 1024 + bn + ncol;
    const int sB = krow * NPAD + ncol;

    float fa[16], fb[16];

#define GLOADA(T) do {                                                         \
    if (sel < 4) {                                                             \
        const float4* p_ = (const float4*)(X + abase + ((T) >> 1) * st + ((T) & 1) * 32); \
        _Pragma("unroll")                                                      \
        for (int q_ = 0; q_ < 4; q_++) {                                       \
            float4 v_ = p_[q_];                                                \
            fa[4*q_+0] = v_.x; fa[4*q_+1] = v_.y; fa[4*q_+2] = v_.z; fa[4*q_+3] = v_.w; \
        }                                                                      \
    } else {                                                                   \
        const int i0_ = cbase + (T) * 32;                                      \
        const int aw_ = awbase + (T) * 32;                                     \
        _Pragma("unroll")                                                      \
        for (int q_ = 0; q_ < 4; q_++) {                                       \
            float4 h_ = *(const float4*)(g_h + i0_ + 4*q_);                    \
            float4 w_ = *(const float4*)(g_w + i0_ + 4*q_);                    \
            float4 d_ = *(const float4*)(g_d + i0_ + 4*q_);                    \
            float4 c_ = *(const float4*)(g_c + i0_ + 4*q_);                    \
            float4 a0_ = *(const float4*)(g_a + 0*8192 + aw_ + 4*q_);          \
            float4 a1_ = *(const float4*)(g_a + 1*8192 + aw_ + 4*q_);          \
            float4 a2_ = *(const float4*)(g_a + 2*8192 + aw_ + 4*q_);          \
            float4 a3_ = *(const float4*)(g_a + 3*8192 + aw_ + 4*q_);          \
            fa[4*q_+0] = h_.x*a0_.x + w_.x*a1_.x + d_.x*a2_.x + c_.x*a3_.x;    \
            fa[4*q_+1] = h_.y*a0_.y + w_.y*a1_.y + d_.y*a2_.y + c_.y*a3_.y;    \
            fa[4*q_+2] = h_.z*a0_.z + w_.z*a1_.z + d_.z*a2_.z + c_.z*a3_.z;    \
            fa[4*q_+3] = h_.w*a0_.w + w_.w*a1_.w + d_.w*a2_.w + c_.w*a3_.w;    \
        }                                                                      \
    }                                                                          \
} while (0)

#define GLOADB(T) do {                                                         \
    const float4* p_ = (const float4*)(Wm + bbase + (T) * 32 * 1024);          \
    _Pragma("unroll")                                                          \
    for (int q_ = 0; q_ < 4; q_++) {                                           \
        float4 v_ = p_[q_];                                                    \
        fb[4*q_+0] = v_.x; fb[4*q_+1] = v_.y; fb[4*q_+2] = v_.z; fb[4*q_+3] = v_.w; \
    }                                                                          \
} while (0)

    // ---- warp tiling: 2(m) x 4(n); warp tile 64x32 = 4x2 wmma frags ----
    const int wm = (wid >> 2) * 64;
    const int wn = (wid & 3) * 32;

    wmma::fragment<wmma::accumulator, 16, 16, 16, float> acc[4][2];
#pragma unroll
    for (int mt = 0; mt < 4; mt++)
#pragma unroll
        for (int nt = 0; nt < 2; nt++)
            wmma::fill_fragment(acc[mt][nt], 0.0f);

    GLOADA(0);
    GLOADB(0);

    for (int t = 0; t < 32; t++) {
        if (t) __syncthreads();       // previous chunk's readers done
        cvt16(fa, sAH + sA, sAL + sA);
        cvt16(fb, sBH + sB, sBL + sB);
        __syncthreads();              // tile visible
        if (t < 31) { GLOADA(t + 1); GLOADB(t + 1); }   // prefetch next

#pragma unroll
        for (int ks = 0; ks < 2; ks++) {
            wmma::fragment<wmma::matrix_a, 16, 16, 16, __nv_bfloat16, wmma::row_major> fah[4], fal[4];
            wmma::fragment<wmma::matrix_b, 16, 16, 16, __nv_bfloat16, wmma::row_major> fbh[2], fbl[2];
#pragma unroll
            for (int mt = 0; mt < 4; mt++) {
                wmma::load_matrix_sync(fah[mt], sAH + (wm + mt*16) * KPAD + ks*16, KPAD);
                wmma::load_matrix_sync(fal[mt], sAL + (wm + mt*16) * KPAD + ks*16, KPAD);
            }
#pragma unroll
            for (int nt = 0; nt < 2; nt++) {
                wmma::load_matrix_sync(fbh[nt], sBH + ks*16*NPAD + wn + nt*16, NPAD);
                wmma::load_matrix_sync(fbl[nt], sBL + ks*16*NPAD + wn + nt*16, NPAD);
            }
#pragma unroll
            for (int mt = 0; mt < 4; mt++)
#pragma unroll
                for (int nt = 0; nt < 2; nt++) {
                    wmma::mma_sync(acc[mt][nt], fah[mt], fbh[nt], acc[mt][nt]);
                    wmma::mma_sync(acc[mt][nt], fah[mt], fbl[nt], acc[mt][nt]);
                    wmma::mma_sync(acc[mt][nt], fal[mt], fbh[nt], acc[mt][nt]);
                }
        }
    }

    // ---- epilogue: per-warp smem staging (reuse operand smem), scatter ----
    __syncthreads();
    float* ep = (float*)smem + wid * (16 * EPAD);   // 8 * 2304B = 18432B

    const int n0  = bn + wn;                 // multiple of 32
    const int cc  = (lane & 7) * 4;          // 0..28  (n0&63)+cc <= 60, no 64-crossing
    const int offn = (n0 >> 6) * st + (n0 & 63) + cc;
    const int offc = n0 + cc;                // contiguous (final)
    const float4 bv = *(const float4*)(bias + n0 + cc);

#pragma unroll
    for (int mt = 0; mt < 4; mt++) {
#pragma unroll
        for (int nt = 0; nt < 2; nt++)
            wmma::store_matrix_sync(ep + nt*16, acc[mt][nt], EPAD, wmma::mem_row_major);
        __syncwarp();
#pragma unroll
        for (int i = 0; i < 4; i++) {
            const int rr = i * 4 + (lane >> 3);           // 0..15
            const int m = bm + wm + mt * 16 + rr;
            const float* s = ep + rr * EPAD + cc;
            float4 o;
            o.x = s[0] + bv.x; o.y = s[1] + bv.y;
            o.z = s[2] + bv.z; o.w = s[3] + bv.w;
            const int adr = (sel < 4) ? (row_base(m, s1, s2, s3) + offn)
                                      : (m * 1024 + offc);
            *(float4*)(Y + adr) = o;
        }
        __syncwarp();
    }
#undef GLOADA
#undef GLOADB
}

// ---------------------------------------------------------------------------
// mean over positions (deterministic 2-stage)
// ---------------------------------------------------------------------------
__global__ void reduce1()
{
    const int b = blockIdx.x, pc = blockIdx.y, ch = threadIdx.x;
    const int base = b * 4194304 + pc * 131072 + ch;
    float s = 0.0f;
#pragma unroll 4
    for (int p = 0; p < 128; p++) {
        const int idx = base + p * 1024;
        s += g_h[idx] + g_w[idx] + g_d[idx] + g_c[idx];
    }
    g_partial[(b * 32 + pc) * 1024 + ch] = s;
}
__global__ void reduce2()
{
    const int b = blockIdx.x, ch = threadIdx.x;
    float s = 0.0f;
#pragma unroll
    for (int pc = 0; pc < 32; pc++) s += g_partial[(b * 32 + pc) * 1024 + ch];
    g_sum[b * 1024 + ch] = s;
}

// ---------------------------------------------------------------------------
// Gating MLP + softmax (tiny)
// ---------------------------------------------------------------------------
__global__ __launch_bounds__(256)
void mlp_kernel(const float* __restrict__ w1, const float* __restrict__ b1,
                const float* __restrict__ w2, const float* __restrict__ b2)
{
    __shared__ float sv[1024];
    __shared__ float tt[256];
    __shared__ float zs[4096];
    const int b = blockIdx.x, tid = threadIdx.x;

    for (int c = tid; c < 1024; c += 256)
        sv[c] = g_sum[b * 1024 + c] * (1.0f / 4096.0f);
    __syncthreads();
    {
        float acc = b1[tid];
        for (int k = 0; k < 1024; k++) acc += sv[k] * w1[k * 256 + tid];
        tt[tid] = 0.5f * acc * (1.0f + erff(acc * 0.7071067811865476f));
    }
    __syncthreads();
    for (int n = tid; n < 4096; n += 256) {
        float acc = b2[n];
#pragma unroll 8
        for (int k = 0; k < 256; k++) acc += tt[k] * w2[k * 4096 + n];
        zs[n] = acc;
    }
    __syncthreads();
    for (int c = tid; c < 1024; c += 256) {
        const float v0 = zs[4*c+0], v1 = zs[4*c+1], v2 = zs[4*c+2], v3 = zs[4*c+3];
        const float mx = fmaxf(fmaxf(v0, v1), fmaxf(v2, v3));
        const float e0 = expf(v0-mx), e1 = expf(v1-mx), e2 = expf(v2-mx), e3 = expf(v3-mx);
        const float inv = 1.0f / (e0 + e1 + e2 + e3);
        g_a[0*8192 + b*1024 + c] = e0 * inv;
        g_a[1*8192 + b*1024 + c] = e1 * inv;
        g_a[2*8192 + b*1024 + c] = e2 * inv;
        g_a[3*8192 + b*1024 + c] = e3 * inv;
    }
}

// ---------------------------------------------------------------------------
extern "C" void kernel_launch(void* const* d_in, const int* in_sizes, int n_in,
                              void* d_out, int out_size)
{
    const float* x  = (const float*)d_in[0];
    const float* wh = (const float*)d_in[1];
    const float* bh = (const float*)d_in[2];
    const float* ww = (const float*)d_in[3];
    const float* bw = (const float*)d_in[4];
    const float* wd = (const float*)d_in[5];
    const float* bd = (const float*)d_in[6];
    const float* wc = (const float*)d_in[7];
    const float* bc = (const float*)d_in[8];
    const float* w1 = (const float*)d_in[9];
    const float* b1 = (const float*)d_in[10];
    const float* w2 = (const float*)d_in[11];
    const float* b2 = (const float*)d_in[12];
    const float* wp = (const float*)d_in[13];
    const float* bp = (const float*)d_in[14];
    float* out = (float*)d_out;

    dim3 grid(8, 256);

    // branch GEMMs: h, w, d, c  (fp32 in, split-bf16 wmma inside)
    gemm_wmma<<<grid, 256>>>(x, wh, bh, 0, 64,     16384, 1024, 262144, nullptr);
    gemm_wmma<<<grid, 256>>>(x, ww, bw, 1, 262144, 64,    1024, 16384,  nullptr);
    gemm_wmma<<<grid, 256>>>(x, wd, bd, 2, 262144, 16384, 64,   1024,   nullptr);
    gemm_wmma<<<grid, 256>>>(x, wc, bc, 3, 262144, 16384, 1024, 64,     nullptr);

    // mean + gating
    reduce1<<<dim3(8, 32), 1024>>>();
    reduce2<<<8, 1024>>>();
    mlp_kernel<<<8, 256>>>(w1, b1, w2, b2);

    // final projection with fused weighted combine
    gemm_wmma<<<grid, 256>>>(x, wp, bp, 4, 262144, 16384, 1024, 64, out);
}